// round 7
// baseline (speedup 1.0000x reference)
#include <cuda_runtime.h>
#include <math.h>

// Problem constants (fixed by the reference)
#define NVAR 4000000
#define KFAC 2000000
#define DV 3
#define DC 6
#define EDGES (NVAR * DV)   // 12,000,000

// Scratch (static; allocation-free rule).
// g_t:       t = tanh(Hsx), variable-side edge order (48MB), contiguous.
// g_tf:      t = tanh(Hsx), FACTOR-side edge order (48MB), scattered by K1.
// g_agg_var: per-edge packed factor aggregate, variable-side order (48MB),
//            scattered by K2. pack = pn float bits with low 2 mantissa bits
//            replaced by min(nz,3)  (rel perturbation ~2.4e-7).
__device__ float        g_t[EDGES];
__device__ float        g_tf[EDGES];
__device__ unsigned int g_agg_var[EDGES];

// ---------------------------------------------------------------------------
// Kernel 1: variable -> factor update + tanh + scatter to factor order.
// One thread per variable. Random stores are fire-and-forget and hide under
// the kernel's DRAM streaming (L1tex was only 28% busy here).
// ---------------------------------------------------------------------------
__global__ void __launch_bounds__(256)
var_update_kernel(const float2* __restrict__ ps,
                  const float2* __restrict__ Min,
                  const float*  __restrict__ Hxs_prev,
                  const int*    __restrict__ perm,
                  int n_vars)
{
    int n = blockIdx.x * blockDim.x + threadIdx.x;
    if (n >= n_vars) return;

    float2 m = Min[n];
    float2 p = ps[n];
    float prior = 0.5f * (__logf(m.x) - __logf(m.y))
                + 0.5f * (__logf(p.x) - __logf(p.y));

    float h0 = Hxs_prev[3 * n + 0];
    float h1 = Hxs_prev[3 * n + 1];
    float h2 = Hxs_prev[3 * n + 2];

    int p0 = __ldcs(&perm[3 * n + 0]);
    int p1 = __ldcs(&perm[3 * n + 1]);
    int p2 = __ldcs(&perm[3 * n + 2]);

    bool i0 = isinf(h0), i1 = isinf(h1), i2 = isinf(h2);
    int sure = (int)i0 + (int)i1 + (int)i2;

    float o0, o1, o2;
    if (sure == 0) {
        float ll = (h0 + h1) + h2;
        o0 = prior + ll - h0;
        o1 = prior + ll - h1;
        o2 = prior + ll - h2;
    } else {
        float ll = (i0 ? 0.0f : h0) + (i1 ? 0.0f : h1) + (i2 ? 0.0f : h2);
        float ss = (i0 ? h0 : 0.0f) + (i1 ? h1 : 0.0f) + (i2 ? h2 : 0.0f);
        if (sure == 1) {
            float pl = prior + ll;
            o0 = i0 ? pl : ss;
            o1 = i1 ? pl : ss;
            o2 = i2 ? pl : ss;
        } else {
            float v = isnan(ss) ? 0.0f : (prior + ss);
            o0 = v; o1 = v; o2 = v;
        }
    }

    float t0 = tanhf(o0), t1 = tanhf(o1), t2 = tanhf(o2);

    // contiguous copy for K3 (self-term)
    g_t[3 * n + 0] = t0;
    g_t[3 * n + 1] = t1;
    g_t[3 * n + 2] = t2;
    // scattered copy for K2 (factor-side contiguous reads)
    __stcg(&g_tf[p0], t0);
    __stcg(&g_tf[p1], t1);
    __stcg(&g_tf[p2], t2);
}

// ---------------------------------------------------------------------------
// Kernel 2: factor aggregates. 2 factors per thread. Contiguous t reads,
// contiguous index reads, random packed-aggregate scatters (fire-and-forget).
// pn = sign * prod of nonzero t's; nz = count of t==0 (clamped to 3).
// ---------------------------------------------------------------------------
__device__ __forceinline__ unsigned int pack_agg(float pn, int nz)
{
    return (__float_as_uint(pn) & ~3u) | (unsigned int)(nz < 3 ? nz : 3);
}

__global__ void __launch_bounds__(256)
fac_aggregate_kernel(const int* __restrict__ inv_perm,
                     const int* __restrict__ x,
                     int n_half)   // n_fac / 2
{
    int t = blockIdx.x * blockDim.x + threadIdx.x;
    if (t >= n_half) return;

    // 12 t-values for 2 factors, contiguous (48B aligned)
    const float4* tf4 = (const float4*)(g_tf + 12 * t);
    float4 v0 = __ldcs(tf4 + 0);
    float4 v1 = __ldcs(tf4 + 1);
    float4 v2 = __ldcs(tf4 + 2);
    float v[12] = {v0.x, v0.y, v0.z, v0.w,
                   v1.x, v1.y, v1.z, v1.w,
                   v2.x, v2.y, v2.z, v2.w};

    const int4* ip4 = (const int4*)(inv_perm + 12 * t);
    int4 a0 = __ldcs(ip4 + 0);
    int4 a1 = __ldcs(ip4 + 1);
    int4 a2 = __ldcs(ip4 + 2);
    int idx[12] = {a0.x, a0.y, a0.z, a0.w,
                   a1.x, a1.y, a1.z, a1.w,
                   a2.x, a2.y, a2.z, a2.w};

    int2 xx = __ldcs((const int2*)(x + 2 * t));
    float pn0 = 1.0f - 2.0f * (float)xx.x;
    float pn1 = 1.0f - 2.0f * (float)xx.y;

    int nz0 = 0, nz1 = 0;
#pragma unroll
    for (int k = 0; k < 6; k++) {
        bool z = (v[k] == 0.0f);
        nz0 += (int)z;
        pn0 *= z ? 1.0f : v[k];
    }
#pragma unroll
    for (int k = 6; k < 12; k++) {
        bool z = (v[k] == 0.0f);
        nz1 += (int)z;
        pn1 *= z ? 1.0f : v[k];
    }

    unsigned int w0 = pack_agg(pn0, nz0);
    unsigned int w1 = pack_agg(pn1, nz1);

    // scatter the factor aggregate to each of its 6 variable-side edge slots
#pragma unroll
    for (int k = 0; k < 6; k++)  __stcg(&g_agg_var[idx[k]], w0);
#pragma unroll
    for (int k = 6; k < 12; k++) __stcg(&g_agg_var[idx[k]], w1);
}

// ---------------------------------------------------------------------------
// per-edge message from self-tanh + packed factor aggregate.
// atanh(pn/t) = 0.5*log((t+pn)/(t-pn)) (sign-safe; |pn|=|t| -> +-inf;
// |pn|>|t| -> nan; matches reference semantics).
// ---------------------------------------------------------------------------
__device__ __forceinline__ float edge_msg(float ts, unsigned int w)
{
    int nz = (int)(w & 3u);
    float pn = __uint_as_float(w & ~3u);
    float r = 0.0f;
    if (nz == 0) {
        r = 0.5f * __logf(__fdividef(ts + pn, ts - pn));
    } else if (nz == 1) {
        if (ts == 0.0f)
            r = 0.5f * __logf(__fdividef(1.0f + pn, 1.0f - pn));
    }
    return r;
}

__device__ __forceinline__ float belief(float h0, float h1, float h2)
{
    float s = (h0 + h1) + h2;
    float d = tanhf(s);
    if (isnan(d)) {
        bool c0 = isinf(h0), c1 = isinf(h1), c2 = isinf(h2);
        if (c0 | c1 | c2) {
            float s2 = (c0 ? 0.0f : h0) + (c1 ? 0.0f : h1) + (c2 ? 0.0f : h2);
            d = tanhf(s2);
        }
    }
    return d;
}

// ---------------------------------------------------------------------------
// Kernel 3: output beliefs. One thread per variable. ZERO random accesses:
// g_t and g_agg_var both contiguous in variable-side edge order.
// ---------------------------------------------------------------------------
__global__ void __launch_bounds__(256)
output_kernel(float2* __restrict__ Mout, int n_vars)
{
    int n = blockIdx.x * blockDim.x + threadIdx.x;
    if (n >= n_vars) return;

    float t0 = g_t[3 * n + 0];
    float t1 = g_t[3 * n + 1];
    float t2 = g_t[3 * n + 2];

    unsigned int w0 = g_agg_var[3 * n + 0];
    unsigned int w1 = g_agg_var[3 * n + 1];
    unsigned int w2 = g_agg_var[3 * n + 2];

    float m0 = edge_msg(t0, w0);
    float m1 = edge_msg(t1, w1);
    float m2 = edge_msg(t2, w2);

    float d = belief(m0, m1, m2);

    float2 o;
    o.x = 0.5f + 0.5f * d;
    o.y = 0.5f - 0.5f * d;
    Mout[n] = o;
}

// ---------------------------------------------------------------------------
// Launch. Inputs: ps[N,2] f32, Min[N,2] f32, Hxs_prev[N,3] f32, x[K,1] i32,
// perm[E] i32, inv_perm[E] i32. Output: M_out[N,2] f32.
// ---------------------------------------------------------------------------
extern "C" void kernel_launch(void* const* d_in, const int* in_sizes, int n_in,
                              void* d_out, int out_size)
{
    const float2* ps       = (const float2*)d_in[0];
    const float2* Min      = (const float2*)d_in[1];
    const float*  Hxs_prev = (const float*)d_in[2];
    const int*    x        = (const int*)d_in[3];
    const int*    perm     = (const int*)d_in[4];
    const int*    inv_perm = (const int*)d_in[5];

    int n_vars = in_sizes[0] / 2;   // 4,000,000
    int n_fac  = in_sizes[3];       // 2,000,000
    int n_half = n_fac / 2;         // 1,000,000

    const int T = 256;
    var_update_kernel<<<(n_vars + T - 1) / T, T>>>(ps, Min, Hxs_prev, perm, n_vars);
    fac_aggregate_kernel<<<(n_half + T - 1) / T, T>>>(inv_perm, x, n_half);
    output_kernel<<<(n_vars + T - 1) / T, T>>>((float2*)d_out, n_vars);
}

// round 8
// speedup vs baseline: 1.8877x; 1.8877x over previous
#include <cuda_runtime.h>
#include <math.h>

// Problem constants (fixed by the reference)
#define NVAR 4000000
#define KFAC 2000000
#define DV 3
#define DC 6
#define EDGES (NVAR * DV)   // 12,000,000

// Scratch (static; allocation-free rule).
// g_t:   t = tanh(Hsx) per edge, variable-side order (48MB). L2-resident
//        target of K2's random gathers.
// g_agg: per-factor packed aggregate (8MB): pn float bits with the low 2
//        mantissa bits replaced by min(nz,3). L2/L1-resident target of K3's
//        random gathers.
__device__ float        g_t[EDGES];
__device__ unsigned int g_agg[KFAC];

// ---------------------------------------------------------------------------
// Kernel 1: variable -> factor update fused with tanh. One thread/variable
// (measured fastest form).
// ---------------------------------------------------------------------------
__global__ void __launch_bounds__(256)
var_update_kernel(const float2* __restrict__ ps,
                  const float2* __restrict__ Min,
                  const float*  __restrict__ Hxs_prev,
                  int n_vars)
{
    int n = blockIdx.x * blockDim.x + threadIdx.x;
    if (n >= n_vars) return;

    float2 m = __ldcs(&Min[n]);
    float2 p = __ldcs(&ps[n]);
    float prior = 0.5f * (__logf(m.x) - __logf(m.y))
                + 0.5f * (__logf(p.x) - __logf(p.y));

    float h0 = __ldcs(&Hxs_prev[3 * n + 0]);
    float h1 = __ldcs(&Hxs_prev[3 * n + 1]);
    float h2 = __ldcs(&Hxs_prev[3 * n + 2]);

    bool i0 = isinf(h0), i1 = isinf(h1), i2 = isinf(h2);
    int sure = (int)i0 + (int)i1 + (int)i2;

    float o0, o1, o2;
    if (sure == 0) {
        float ll = (h0 + h1) + h2;
        o0 = prior + ll - h0;
        o1 = prior + ll - h1;
        o2 = prior + ll - h2;
    } else {
        float ll = (i0 ? 0.0f : h0) + (i1 ? 0.0f : h1) + (i2 ? 0.0f : h2);
        float ss = (i0 ? h0 : 0.0f) + (i1 ? h1 : 0.0f) + (i2 ? h2 : 0.0f);
        if (sure == 1) {
            float pl = prior + ll;
            o0 = i0 ? pl : ss;
            o1 = i1 ? pl : ss;
            o2 = i2 ? pl : ss;
        } else {
            float v = isnan(ss) ? 0.0f : (prior + ss);
            o0 = v; o1 = v; o2 = v;
        }
    }
    // store tanh(Hsx): tanh(+-inf)=+-1, tanh(nan)=nan -> semantics preserved
    g_t[3 * n + 0] = tanhf(o0);
    g_t[3 * n + 1] = tanhf(o1);
    g_t[3 * n + 2] = tanhf(o2);
}

// ---------------------------------------------------------------------------
// Kernel 2: factor aggregates. 4 factors per thread -> 24 random gathers
// issued back-to-back (deep MLP). Indices streamed via __ldcs (int4).
// Output: packed {pn, nz} per factor, contiguous 4B.
// ---------------------------------------------------------------------------
__device__ __forceinline__ unsigned int pack_agg(float pn, int nz)
{
    return (__float_as_uint(pn) & ~3u) | (unsigned int)(nz < 3 ? nz : 3);
}

__global__ void __launch_bounds__(256)
fac_aggregate_kernel(const int* __restrict__ inv_perm,
                     const int* __restrict__ x,
                     int n_quad)   // n_fac / 4
{
    int t = blockIdx.x * blockDim.x + threadIdx.x;
    if (t >= n_quad) return;

    // 24 indices for 4 factors (96B, aligned)
    const int4* ip4 = (const int4*)(inv_perm + 24 * t);
    int idx[24];
#pragma unroll
    for (int q = 0; q < 6; q++) {
        int4 a = __ldcs(ip4 + q);
        idx[4 * q + 0] = a.x; idx[4 * q + 1] = a.y;
        idx[4 * q + 2] = a.z; idx[4 * q + 3] = a.w;
    }

    // all 24 gathers back-to-back
    float v[24];
#pragma unroll
    for (int k = 0; k < 24; k++)
        v[k] = __ldcg(&g_t[idx[k]]);

    int4 xx = __ldcs((const int4*)(x + 4 * t));
    float sgn[4] = {1.0f - 2.0f * (float)xx.x, 1.0f - 2.0f * (float)xx.y,
                    1.0f - 2.0f * (float)xx.z, 1.0f - 2.0f * (float)xx.w};

    unsigned int w[4];
#pragma unroll
    for (int f = 0; f < 4; f++) {
        float pn = sgn[f];
        int nz = 0;
#pragma unroll
        for (int k = 0; k < 6; k++) {
            float tv = v[6 * f + k];
            bool z = (tv == 0.0f);
            nz += (int)z;
            pn *= z ? 1.0f : tv;
        }
        w[f] = pack_agg(pn, nz);
    }

    uint4 outw = make_uint4(w[0], w[1], w[2], w[3]);
    *(uint4*)&g_agg[4 * t] = outw;
}

// ---------------------------------------------------------------------------
// per-edge message from self-tanh + packed factor aggregate.
// atanh(pn/t) = 0.5*log((t+pn)/(t-pn)):
//   sign-safe; |pn|==|t| -> +-inf; |pn|>|t| -> nan; nan pn propagates.
// ---------------------------------------------------------------------------
__device__ __forceinline__ float edge_msg(float ts, unsigned int w)
{
    int nz = (int)(w & 3u);
    float pn = __uint_as_float(w & ~3u);
    float r = 0.0f;
    if (nz == 0) {
        r = 0.5f * __logf(__fdividef(ts + pn, ts - pn));
    } else if (nz == 1) {
        if (ts == 0.0f)
            r = 0.5f * __logf(__fdividef(1.0f + pn, 1.0f - pn));
    }
    return r;
}

__device__ __forceinline__ float belief(float h0, float h1, float h2)
{
    float s = (h0 + h1) + h2;
    float d = tanhf(s);
    if (isnan(d)) {
        bool c0 = isinf(h0), c1 = isinf(h1), c2 = isinf(h2);
        if (c0 | c1 | c2) {
            float s2 = (c0 ? 0.0f : h0) + (c1 ? 0.0f : h1) + (c2 ? 0.0f : h2);
            d = tanhf(s2);
        }
    }
    return d;
}

// ---------------------------------------------------------------------------
// Kernel 3: output beliefs. 2 variables per thread -> 6 back-to-back 4B
// gathers from the 8MB L2/L1-resident aggregate array. Everything else is
// streamed (g_t, perm via __ldcs; float4 output).
// ---------------------------------------------------------------------------
__global__ void __launch_bounds__(256)
output_kernel(const int* __restrict__ perm,
              float4* __restrict__ Mout,
              int n_pair)   // n_vars / 2
{
    int t = blockIdx.x * blockDim.x + threadIdx.x;
    if (t >= n_pair) return;

    const int2* pp = (const int2*)(perm + 6 * t);
    int2 e0 = __ldcs(pp + 0);
    int2 e1 = __ldcs(pp + 1);
    int2 e2 = __ldcs(pp + 2);

    // factor ids (perm value = factor-side slot 6a+k); 6 gathers back-to-back
    unsigned int w0 = __ldg(&g_agg[e0.x / 6]);
    unsigned int w1 = __ldg(&g_agg[e0.y / 6]);
    unsigned int w2 = __ldg(&g_agg[e1.x / 6]);
    unsigned int w3 = __ldg(&g_agg[e1.y / 6]);
    unsigned int w4 = __ldg(&g_agg[e2.x / 6]);
    unsigned int w5 = __ldg(&g_agg[e2.y / 6]);

    const float2* tt = (const float2*)(g_t + 6 * t);
    float2 ta = __ldcs(tt + 0);
    float2 tb = __ldcs(tt + 1);
    float2 tc = __ldcs(tt + 2);

    float m0 = edge_msg(ta.x, w0);
    float m1 = edge_msg(ta.y, w1);
    float m2 = edge_msg(tb.x, w2);
    float m3 = edge_msg(tb.y, w3);
    float m4 = edge_msg(tc.x, w4);
    float m5 = edge_msg(tc.y, w5);

    float d0 = belief(m0, m1, m2);
    float d1 = belief(m3, m4, m5);

    float4 o;
    o.x = 0.5f + 0.5f * d0;  o.y = 0.5f - 0.5f * d0;
    o.z = 0.5f + 0.5f * d1;  o.w = 0.5f - 0.5f * d1;
    Mout[t] = o;
}

// ---------------------------------------------------------------------------
// Launch. Inputs: ps[N,2] f32, Min[N,2] f32, Hxs_prev[N,3] f32, x[K,1] i32,
// perm[E] i32, inv_perm[E] i32. Output: M_out[N,2] f32.
// ---------------------------------------------------------------------------
extern "C" void kernel_launch(void* const* d_in, const int* in_sizes, int n_in,
                              void* d_out, int out_size)
{
    const float2* ps       = (const float2*)d_in[0];
    const float2* Min      = (const float2*)d_in[1];
    const float*  Hxs_prev = (const float*)d_in[2];
    const int*    x        = (const int*)d_in[3];
    const int*    perm     = (const int*)d_in[4];
    const int*    inv_perm = (const int*)d_in[5];

    int n_vars = in_sizes[0] / 2;   // 4,000,000
    int n_fac  = in_sizes[3];       // 2,000,000
    int n_quad = n_fac / 4;         // 500,000
    int n_pair = n_vars / 2;        // 2,000,000

    const int T = 256;
    var_update_kernel<<<(n_vars + T - 1) / T, T>>>(ps, Min, Hxs_prev, n_vars);
    fac_aggregate_kernel<<<(n_quad + T - 1) / T, T>>>(inv_perm, x, n_quad);
    output_kernel<<<(n_pair + T - 1) / T, T>>>(perm, (float4*)d_out, n_pair);
}

// round 9
// speedup vs baseline: 1.9211x; 1.0177x over previous
#include <cuda_runtime.h>
#include <math.h>

// Problem constants (fixed by the reference)
#define NVAR 4000000
#define KFAC 2000000
#define DV 3
#define DC 6
#define EDGES (NVAR * DV)   // 12,000,000

// Scratch (static; allocation-free rule).
// g_t:   t = tanh(Hsx) per edge, variable-side order (48MB). L2-resident
//        target of K2's random gathers.
// g_agg: per-factor packed aggregate (8MB): pn float bits with the low 2
//        mantissa bits replaced by min(nz,3) (rel perturbation ~2.4e-7).
__device__ float        g_t[EDGES];
__device__ unsigned int g_agg[KFAC];

// ---------------------------------------------------------------------------
// Kernel 1: variable -> factor update fused with tanh. One thread/variable.
// prior computed with a single log: 0.5*log((mx*px)/(my*py)).
// ---------------------------------------------------------------------------
__global__ void __launch_bounds__(256)
var_update_kernel(const float2* __restrict__ ps,
                  const float2* __restrict__ Min,
                  const float*  __restrict__ Hxs_prev,
                  int n_vars)
{
    int n = blockIdx.x * blockDim.x + threadIdx.x;
    if (n >= n_vars) return;

    float2 m = Min[n];
    float2 p = ps[n];
    float prior = 0.5f * __logf(__fdividef(m.x * p.x, m.y * p.y));

    float h0 = Hxs_prev[3 * n + 0];
    float h1 = Hxs_prev[3 * n + 1];
    float h2 = Hxs_prev[3 * n + 2];

    bool i0 = isinf(h0), i1 = isinf(h1), i2 = isinf(h2);
    int sure = (int)i0 + (int)i1 + (int)i2;

    float o0, o1, o2;
    if (sure == 0) {
        float ll = (h0 + h1) + h2;
        o0 = prior + ll - h0;
        o1 = prior + ll - h1;
        o2 = prior + ll - h2;
    } else {
        float ll = (i0 ? 0.0f : h0) + (i1 ? 0.0f : h1) + (i2 ? 0.0f : h2);
        float ss = (i0 ? h0 : 0.0f) + (i1 ? h1 : 0.0f) + (i2 ? h2 : 0.0f);
        if (sure == 1) {
            float pl = prior + ll;
            o0 = i0 ? pl : ss;
            o1 = i1 ? pl : ss;
            o2 = i2 ? pl : ss;
        } else {
            float v = isnan(ss) ? 0.0f : (prior + ss);
            o0 = v; o1 = v; o2 = v;
        }
    }
    // store tanh(Hsx): tanh(+-inf)=+-1, tanh(nan)=nan -> semantics preserved
    g_t[3 * n + 0] = tanhf(o0);
    g_t[3 * n + 1] = tanhf(o1);
    g_t[3 * n + 2] = tanhf(o2);
}

// ---------------------------------------------------------------------------
// Kernel 2: factor aggregates. 2 factors per thread, block=128 (more CTAs,
// better SM balance; L1tex queue fed by many warps). Gathers via __ldg so
// L1 can capture sector reuse (~8 reads/sector globally).
// ---------------------------------------------------------------------------
__device__ __forceinline__ unsigned int pack_agg(float pn, int nz)
{
    return (__float_as_uint(pn) & ~3u) | (unsigned int)(nz < 3 ? nz : 3);
}

__global__ void __launch_bounds__(128)
fac_aggregate_kernel(const int* __restrict__ inv_perm,
                     const int* __restrict__ x,
                     int n_half)   // n_fac / 2
{
    int t = blockIdx.x * blockDim.x + threadIdx.x;
    if (t >= n_half) return;

    const int4* ip4 = (const int4*)(inv_perm + 12 * t);   // 48B-aligned
    int4 a0 = __ldcs(ip4 + 0);
    int4 a1 = __ldcs(ip4 + 1);
    int4 a2 = __ldcs(ip4 + 2);
    int idx[12] = {a0.x, a0.y, a0.z, a0.w,
                   a1.x, a1.y, a1.z, a1.w,
                   a2.x, a2.y, a2.z, a2.w};

    float v[12];
#pragma unroll
    for (int k = 0; k < 12; k++)
        v[k] = __ldg(&g_t[idx[k]]);

    int2 xx = __ldcs((const int2*)(x + 2 * t));
    float pn0 = 1.0f - 2.0f * (float)xx.x;
    float pn1 = 1.0f - 2.0f * (float)xx.y;

    int nz0 = 0, nz1 = 0;
#pragma unroll
    for (int k = 0; k < 6; k++) {
        bool z = (v[k] == 0.0f);
        nz0 += (int)z;
        pn0 *= z ? 1.0f : v[k];
    }
#pragma unroll
    for (int k = 6; k < 12; k++) {
        bool z = (v[k] == 0.0f);
        nz1 += (int)z;
        pn1 *= z ? 1.0f : v[k];
    }

    uint2 outw = make_uint2(pack_agg(pn0, nz0), pack_agg(pn1, nz1));
    *(uint2*)&g_agg[2 * t] = outw;
}

// ---------------------------------------------------------------------------
// per-edge message from self-tanh + packed factor aggregate.
// atanh(pn/t) = 0.5*log((t+pn)/(t-pn)):
//   sign-safe; |pn|==|t| -> +-inf; |pn|>|t| -> nan; nan pn propagates.
// ---------------------------------------------------------------------------
__device__ __forceinline__ float edge_msg(float ts, unsigned int w)
{
    int nz = (int)(w & 3u);
    float pn = __uint_as_float(w & ~3u);
    float r = 0.0f;
    if (nz == 0) {
        r = 0.5f * __logf(__fdividef(ts + pn, ts - pn));
    } else if (nz == 1) {
        if (ts == 0.0f)
            r = 0.5f * __logf(__fdividef(1.0f + pn, 1.0f - pn));
    }
    return r;
}

__device__ __forceinline__ float belief(float h0, float h1, float h2)
{
    float s = (h0 + h1) + h2;
    float d = tanhf(s);
    if (isnan(d)) {
        bool c0 = isinf(h0), c1 = isinf(h1), c2 = isinf(h2);
        if (c0 | c1 | c2) {
            float s2 = (c0 ? 0.0f : h0) + (c1 ? 0.0f : h1) + (c2 ? 0.0f : h2);
            d = tanhf(s2);
        }
    }
    return d;
}

// ---------------------------------------------------------------------------
// Kernel 3: output beliefs. One thread per variable, block=128 (max TLP).
// 3 back-to-back 4B gathers from the 8MB aggregate array via __ldg
// (~6 reads/word globally -> some L1 capture). Streams via __ldcs.
// ---------------------------------------------------------------------------
__global__ void __launch_bounds__(128)
output_kernel(const int* __restrict__ perm,
              float2* __restrict__ Mout,
              int n_vars)
{
    int n = blockIdx.x * blockDim.x + threadIdx.x;
    if (n >= n_vars) return;

    int e0 = __ldcs(&perm[3 * n + 0]);
    int e1 = __ldcs(&perm[3 * n + 1]);
    int e2 = __ldcs(&perm[3 * n + 2]);

    // factor ids (perm value = factor-side slot 6a+k); gathers back-to-back
    unsigned int w0 = __ldg(&g_agg[e0 / 6]);
    unsigned int w1 = __ldg(&g_agg[e1 / 6]);
    unsigned int w2 = __ldg(&g_agg[e2 / 6]);

    float t0 = __ldcs(&g_t[3 * n + 0]);
    float t1 = __ldcs(&g_t[3 * n + 1]);
    float t2 = __ldcs(&g_t[3 * n + 2]);

    float m0 = edge_msg(t0, w0);
    float m1 = edge_msg(t1, w1);
    float m2 = edge_msg(t2, w2);

    float d = belief(m0, m1, m2);

    float2 o;
    o.x = 0.5f + 0.5f * d;
    o.y = 0.5f - 0.5f * d;
    Mout[n] = o;
}

// ---------------------------------------------------------------------------
// Launch. Inputs: ps[N,2] f32, Min[N,2] f32, Hxs_prev[N,3] f32, x[K,1] i32,
// perm[E] i32, inv_perm[E] i32. Output: M_out[N,2] f32.
// ---------------------------------------------------------------------------
extern "C" void kernel_launch(void* const* d_in, const int* in_sizes, int n_in,
                              void* d_out, int out_size)
{
    const float2* ps       = (const float2*)d_in[0];
    const float2* Min      = (const float2*)d_in[1];
    const float*  Hxs_prev = (const float*)d_in[2];
    const int*    x        = (const int*)d_in[3];
    const int*    perm     = (const int*)d_in[4];
    const int*    inv_perm = (const int*)d_in[5];

    int n_vars = in_sizes[0] / 2;   // 4,000,000
    int n_fac  = in_sizes[3];       // 2,000,000
    int n_half = n_fac / 2;         // 1,000,000

    var_update_kernel<<<(n_vars + 255) / 256, 256>>>(ps, Min, Hxs_prev, n_vars);
    fac_aggregate_kernel<<<(n_half + 127) / 128, 128>>>(inv_perm, x, n_half);
    output_kernel<<<(n_vars + 127) / 128, 128>>>(perm, (float2*)d_out, n_vars);
}